// round 1
// baseline (speedup 1.0000x reference)
#include <cuda_runtime.h>

// BinaryConv2d: out[n,o,h,w] = sum_{c,kh,kw} x[n,c,h+kh-1,w+kw-1] * sign(W[o,c,kh,kw]) + bias[o]
// x: [32,128,56,56] f32, W: [256,128,3,3] f32, bias: [256] f32, out: [32,256,56,56] f32

#define N_BATCH 32
#define C_IN    128
#define C_OUT   256
#define HW      56
#define OCB     64   // output channels per block
#define CK      16   // input-channel chunk

// Pre-binarized, transposed weights: layout [ (c*9 + k) ][ oc ]  (k = kh*3+kw)
__device__ float g_wb[C_IN * 9 * C_OUT];

__global__ void binarize_weights_kernel(const float* __restrict__ w) {
    int idx = blockIdx.x * blockDim.x + threadIdx.x;   // over 256*128*9
    if (idx >= C_OUT * C_IN * 9) return;
    int oc  = idx / (C_IN * 9);
    int rem = idx - oc * (C_IN * 9);                   // c*9 + k
    float v = w[idx];
    // clip(-1,1) then sign with sign(0)->+1  ==  (v >= 0 ? +1 : -1)
    g_wb[rem * C_OUT + oc] = (v >= 0.0f) ? 1.0f : -1.0f;
}

__global__ __launch_bounds__(128)
void binary_conv2d_kernel(const float* __restrict__ x,
                          const float* __restrict__ bias,
                          float* __restrict__ out) {
    // Input tile: CK channels x 3 rows x 58 cols (w_in = -1..56 stored at col = w_in+1), padded stride 60
    __shared__ float sx[CK][3][60];
    // Weight tile: [c*9+k][oc]
    __shared__ float sw[CK * 9][OCB];

    const int ocBase = blockIdx.x * OCB;
    const int h      = blockIdx.y;
    const int n      = blockIdx.z;
    const int tid    = threadIdx.x;

    const int oc_i   = tid >> 3;        // 0..15
    const int w_grp  = tid & 7;         // 0..7
    const int w_base = w_grp * 7;       // 7 outputs per thread in w

    float acc[4][7];
#pragma unroll
    for (int ii = 0; ii < 4; ii++)
#pragma unroll
        for (int j = 0; j < 7; j++) acc[ii][j] = 0.0f;

    for (int cc = 0; cc < C_IN; cc += CK) {
        __syncthreads();   // protect smem from previous iteration's readers

        // ---- load input tile (coalesced along w) ----
        for (int idx = tid; idx < CK * 3 * 58; idx += 128) {
            int c   = idx / (3 * 58);
            int r   = (idx / 58) % 3;
            int col = idx % 58;
            int hin = h + r - 1;
            int win = col - 1;
            float v = 0.0f;
            if ((unsigned)hin < HW && (unsigned)win < HW)
                v = x[(((n * C_IN + cc + c) * HW) + hin) * HW + win];
            sx[c][r][col] = v;
        }

        // ---- load binarized weight tile (coalesced in oc, conflict-free STS) ----
        const float* wb = g_wb + (size_t)cc * 9 * C_OUT + ocBase;
        for (int idx = tid; idx < CK * 9 * OCB; idx += 128) {
            int row = idx >> 6;          // c*9 + k   (OCB = 64)
            int oc  = idx & (OCB - 1);
            sw[row][oc] = wb[row * C_OUT + oc];
        }

        __syncthreads();

        // ---- compute ----
#pragma unroll
        for (int c = 0; c < CK; c++) {
#pragma unroll
            for (int kh = 0; kh < 3; kh++) {
                float xv[9];
#pragma unroll
                for (int j = 0; j < 9; j++) xv[j] = sx[c][kh][w_base + j];
#pragma unroll
                for (int ii = 0; ii < 4; ii++) {
                    const int oc = oc_i + 16 * ii;
                    const float w0 = sw[c * 9 + kh * 3 + 0][oc];
                    const float w1 = sw[c * 9 + kh * 3 + 1][oc];
                    const float w2 = sw[c * 9 + kh * 3 + 2][oc];
#pragma unroll
                    for (int j = 0; j < 7; j++) {
                        float a = acc[ii][j];
                        a = fmaf(xv[j + 0], w0, a);
                        a = fmaf(xv[j + 1], w1, a);
                        a = fmaf(xv[j + 2], w2, a);
                        acc[ii][j] = a;
                    }
                }
            }
        }
    }

    // ---- epilogue: add bias, store ----
#pragma unroll
    for (int ii = 0; ii < 4; ii++) {
        const int oc = ocBase + oc_i + 16 * ii;
        const float b = __ldg(&bias[oc]);
        float* op = out + (((size_t)n * C_OUT + oc) * HW + h) * HW + w_base;
#pragma unroll
        for (int j = 0; j < 7; j++) op[j] = acc[ii][j] + b;
    }
}

extern "C" void kernel_launch(void* const* d_in, const int* in_sizes, int n_in,
                              void* d_out, int out_size) {
    const float* x      = (const float*)d_in[0];   // [32,128,56,56]
    const float* weight = (const float*)d_in[1];   // [256,128,3,3]
    const float* bias   = (const float*)d_in[2];   // [256]
    float* out          = (float*)d_out;           // [32,256,56,56]

    // 1) binarize + transpose weights into g_wb
    {
        int total = C_OUT * C_IN * 9;
        binarize_weights_kernel<<<(total + 255) / 256, 256>>>(weight);
    }

    // 2) main conv: grid = (oc blocks, h, n)
    {
        dim3 grid(C_OUT / OCB, HW, N_BATCH);
        binary_conv2d_kernel<<<grid, 128>>>(x, bias, out);
    }
}

// round 3
// speedup vs baseline: 1.8896x; 1.8896x over previous
#include <cuda_runtime.h>
#include <cuda_bf16.h>
#include <cstdint>

// BinaryConv2d via mma.sync (HMMA) implicit GEMM, bf16 hi/lo split, fp32 accum.
// out[n,o,h,w] = sum_{c,kh,kw} x[n,c,h+kh-1,w+kw-1]*sign(W[o,c,kh,kw]) + bias[o]

#define NB 32
#define CI 128
#define CO 256
#define HH 56
#define HP 58
#define PIXN (HH*HH)          // 3136
#define NPIX (NB*PIXN)        // 100352
#define KTOT 2304             // 9 taps * 256 (hi128 + lo128)
#define KSTEPS (KTOT/16)      // 144

// padded NHWC bf16, channel = [hi(128), lo(128)]
__device__ __nv_bfloat16 g_xp[(size_t)NB*HP*HP*256];
// binarized weights [oc][k], k = tap*256 + cc (cc<128: hi-c, cc>=128: lo-c, same sign)
__device__ __nv_bfloat16 g_wb[(size_t)CO*KTOT];

// ---------------- transforms ----------------
__global__ void transform_x_kernel(const float* __restrict__ x) {
    int idx = blockIdx.x * blockDim.x + threadIdx.x;   // over NB*HP*HP*CI
    if (idx >= NB * HP * HP * CI) return;
    int c  = idx & 127;
    int t  = idx >> 7;
    int wp = t % HP;
    int hp = (t / HP) % HP;
    int n  = t / (HP * HP);
    int hin = hp - 1, win = wp - 1;
    float v = 0.0f;
    if ((unsigned)hin < HH && (unsigned)win < HH)
        v = x[(((size_t)n * CI + c) * HH + hin) * HH + win];
    __nv_bfloat16 hi = __float2bfloat16_rn(v);
    __nv_bfloat16 lo = __float2bfloat16_rn(v - __bfloat162float(hi));
    size_t base = ((size_t)(n * HP + hp) * HP + wp) * 256;
    g_xp[base + c]       = hi;
    g_xp[base + 128 + c] = lo;
}

__global__ void transform_w_kernel(const float* __restrict__ w) {
    int idx = blockIdx.x * blockDim.x + threadIdx.x;   // over CO*KTOT
    if (idx >= CO * KTOT) return;
    int oc = idx / KTOT;
    int k  = idx - oc * KTOT;
    int tap = k >> 8;
    int c   = k & 127;        // hi and lo planes share the sign
    float v = w[((size_t)oc * CI + c) * 9 + tap];
    g_wb[idx] = __float2bfloat16_rn(v >= 0.0f ? 1.0f : -1.0f);
}

// ---------------- main kernel ----------------
__device__ __forceinline__ uint32_t smem_u32(const void* p) {
    uint32_t a;
    asm("{ .reg .u64 t; cvta.to.shared.u64 t, %1; cvt.u32.u64 %0, t; }" : "=r"(a) : "l"(p));
    return a;
}
__device__ __forceinline__ void cp16(uint32_t dst, const void* src) {
    asm volatile("cp.async.cg.shared.global [%0], [%1], 16;" :: "r"(dst), "l"(src));
}
#define CP_COMMIT() asm volatile("cp.async.commit_group;" ::: "memory")
#define CP_WAIT1()  asm volatile("cp.async.wait_group 1;" ::: "memory")

__device__ __forceinline__ void ldsm4(uint32_t* r, uint32_t addr) {
    asm volatile("ldmatrix.sync.aligned.m8n8.x4.shared.b16 {%0,%1,%2,%3}, [%4];"
        : "=r"(r[0]), "=r"(r[1]), "=r"(r[2]), "=r"(r[3]) : "r"(addr));
}
__device__ __forceinline__ void mma16816(float* c, const uint32_t* a, uint32_t b0, uint32_t b1) {
    asm volatile("mma.sync.aligned.m16n8k16.row.col.f32.bf16.bf16.f32 "
        "{%0,%1,%2,%3}, {%4,%5,%6,%7}, {%8,%9}, {%0,%1,%2,%3};"
        : "+f"(c[0]), "+f"(c[1]), "+f"(c[2]), "+f"(c[3])
        : "r"(a[0]), "r"(a[1]), "r"(a[2]), "r"(a[3]), "r"(b0), "r"(b1));
}

#define STAGES 3

__global__ __launch_bounds__(512, 1)
void binconv_hmma_kernel(const float* __restrict__ bias, float* __restrict__ out) {
    // [stage][kblk(2)][row][8 bf16 = 16B] — ldmatrix conflict-free
    __shared__ __align__(1024) __nv_bfloat16 sA[STAGES][2][128][8];
    __shared__ __align__(1024) __nv_bfloat16 sB[STAGES][2][256][8];

    const int tid  = threadIdx.x;
    const int wid  = tid >> 5;
    const int lane = tid & 31;
    const int q0   = blockIdx.x * 128;

    const uint32_t sAb = smem_u32(&sA[0][0][0][0]);
    const uint32_t sBb = smem_u32(&sB[0][0][0][0]);

    // A-producer per-thread source base (threads 0..255 load A)
    const int apix  = tid >> 1;          // 0..255 -> pixel 0..127 (x2)
    const int ahalf = tid & 1;
    size_t a_src_base = 0;
    if (tid < 256) {
        int q  = q0 + apix;
        int n_ = q / PIXN;
        int r_ = q - n_ * PIXN;
        int h_ = r_ / HH;
        int w_ = r_ - h_ * HH;
        a_src_base = ((size_t)(n_ * HP + h_) * HP + w_) * 256 + ahalf * 8;
    }
    // B-producer
    const int boc   = tid >> 1;
    const int bhalf = tid & 1;
    const size_t b_src_base = (size_t)boc * KTOT + bhalf * 8;

    const uint32_t a_dst0 = sAb + (uint32_t)(ahalf * 128 + apix) * 16;
    const uint32_t b_dst0 = sBb + (uint32_t)(bhalf * 256 + boc) * 16;

    // warp tiling: 4 (M) x 4 (N)
    const int wm = (wid & 3) * 32;
    const int wn = (wid >> 2) * 64;

    float acc[2][8][4];
#pragma unroll
    for (int mi = 0; mi < 2; mi++)
#pragma unroll
        for (int nb = 0; nb < 8; nb++)
#pragma unroll
            for (int j = 0; j < 4; j++) acc[mi][nb][j] = 0.0f;

    auto issue = [&](int it) {
        const int stage = it % STAGES;
        const int tap = it >> 4;
        const int dh = tap / 3, dw = tap - dh * 3;
        const int cc = (it & 15) * 16;
        if (tid < 256) {
            const __nv_bfloat16* src = g_xp + a_src_base + ((size_t)dh * HP + dw) * 256 + cc;
            cp16(a_dst0 + stage * 4096, src);
        }
        {
            const __nv_bfloat16* src = g_wb + b_src_base + it * 16;
            cp16(b_dst0 + stage * 8192, src);
        }
        CP_COMMIT();
    };

    issue(0);
    issue(1);

    // ldmatrix lane addressing (constant offsets)
    const uint32_t a_lrow = (uint32_t)((lane >> 4) * 128 + (lane & 15)) * 16;            // + (wm+mi*16)*16
    const uint32_t b_lrow = (uint32_t)(((lane >> 3) & 1) * 256 + (lane & 7) + ((lane >> 4) << 3)) * 16; // + (wn+nj*16)*16

    for (int it = 0; it < KSTEPS; it++) {
        const int s = it % STAGES;
        CP_WAIT1();
        __syncthreads();

        uint32_t af[2][4], bf[4][4];
#pragma unroll
        for (int mi = 0; mi < 2; mi++)
            ldsm4(af[mi], sAb + (uint32_t)s * 4096 + a_lrow + (uint32_t)(wm + mi * 16) * 16);
#pragma unroll
        for (int nj = 0; nj < 4; nj++)
            ldsm4(bf[nj], sBb + (uint32_t)s * 8192 + b_lrow + (uint32_t)(wn + nj * 16) * 16);

#pragma unroll
        for (int mi = 0; mi < 2; mi++)
#pragma unroll
            for (int nb = 0; nb < 8; nb++) {
                const uint32_t* bp = bf[nb >> 1];
                if (nb & 1) mma16816(acc[mi][nb], af[mi], bp[2], bp[3]);
                else        mma16816(acc[mi][nb], af[mi], bp[0], bp[1]);
            }

        __syncthreads();
        if (it + 2 < KSTEPS) issue(it + 2);
    }

    // ---------------- epilogue: fused bias, coalesced NCHW stores ----------------
    const int qr  = lane >> 2;           // 0..7 (pixel within 8)
    const int oc2 = (lane & 3) * 2;      // oc pair offset

    float2 bv[8];
#pragma unroll
    for (int nb = 0; nb < 8; nb++)
        bv[nb] = *(const float2*)(bias + wn + nb * 8 + oc2);

#pragma unroll
    for (int mi = 0; mi < 2; mi++) {
#pragma unroll
        for (int half = 0; half < 2; half++) {
            const int p  = q0 + wm + mi * 16 + half * 8 + qr;   // global pixel
            const int n2 = p / PIXN;
            const int rm = p - n2 * PIXN;
            float* ob = out + (size_t)n2 * CO * PIXN + rm;
#pragma unroll
            for (int nb = 0; nb < 8; nb++) {
                const int oc = wn + nb * 8 + oc2;
                ob[(size_t)oc * PIXN]       = acc[mi][nb][half * 2 + 0] + bv[nb].x;
                ob[(size_t)(oc + 1) * PIXN] = acc[mi][nb][half * 2 + 1] + bv[nb].y;
            }
        }
    }
}

// ---------------- launch ----------------
extern "C" void kernel_launch(void* const* d_in, const int* in_sizes, int n_in,
                              void* d_out, int out_size) {
    const float* x      = (const float*)d_in[0];
    const float* weight = (const float*)d_in[1];
    const float* bias   = (const float*)d_in[2];
    float* out          = (float*)d_out;

    {
        int total = NB * HP * HP * CI;
        transform_x_kernel<<<(total + 255) / 256, 256>>>(x);
    }
    {
        int total = CO * KTOT;
        transform_w_kernel<<<(total + 255) / 256, 256>>>(weight);
    }
    binconv_hmma_kernel<<<NPIX / 128, 512>>>(bias, out);
}

// round 4
// speedup vs baseline: 3.3034x; 1.7483x over previous
#include <cuda_runtime.h>
#include <cuda_bf16.h>
#include <cstdint>

// BinaryConv2d via mma.sync (HMMA) implicit GEMM, bf16 hi/lo split, fp32 accum.
// out[n,o,h,w] = sum_{c,kh,kw} x[n,c,h+kh-1,w+kw-1]*sign(W[o,c,kh,kw]) + bias[o]

#define NB 32
#define CI 128
#define CO 256
#define HH 56
#define HP 58
#define PIXN (HH*HH)          // 3136
#define NPIX (NB*PIXN)        // 100352
#define KTOT 2304             // 9 taps * 256 (hi128 + lo128)
#define NITER 36              // K-chunks of 64

// padded NHWC bf16, channel = [hi(128), lo(128)]
__device__ __nv_bfloat16 g_xp[(size_t)NB*HP*HP*256];
// binarized weights [oc][k], k = tap*256 + cc (cc<128: hi-c, cc>=128: lo-c, same sign)
__device__ __nv_bfloat16 g_wb[(size_t)CO*KTOT];

// ---------------- transforms ----------------
// block = (n, hp). Coalesced NCHW read -> smem -> coalesced NHWC write (hi/lo).
__global__ __launch_bounds__(256)
void transform_x_kernel(const float* __restrict__ x) {
    __shared__ float s[128][57];
    const int hp = blockIdx.x % HP;
    const int n  = blockIdx.x / HP;
    const int tid = threadIdx.x;
    const bool interior_h = (hp >= 1 && hp <= HH);

    if (interior_h) {
        const int h = hp - 1;
        const float* src = x + ((size_t)n * CI * HH + h) * HH;   // x[n, c, h, w] = src[c*PIXN + w]
        for (int idx = tid; idx < CI * HH; idx += 256) {
            int c = idx / HH, w = idx - (idx / HH) * HH;
            s[c][w] = src[(size_t)c * PIXN + w];
        }
    }
    __syncthreads();

    const int c = tid & 127;
    const int half = tid >> 7;          // 0 = hi, 1 = lo
    __nv_bfloat16* ob = g_xp + ((size_t)(n * HP + hp) * HP) * 256 + half * 128 + c;
#pragma unroll 2
    for (int wp = 0; wp < HP; wp++) {
        float v = 0.0f;
        if (interior_h && wp >= 1 && wp <= HH) v = s[c][wp - 1];
        __nv_bfloat16 hi = __float2bfloat16_rn(v);
        __nv_bfloat16 o = half ? __float2bfloat16_rn(v - __bfloat162float(hi)) : hi;
        ob[(size_t)wp * 256] = o;
    }
}

__global__ void transform_w_kernel(const float* __restrict__ w) {
    int idx = blockIdx.x * blockDim.x + threadIdx.x;   // over CO*KTOT
    if (idx >= CO * KTOT) return;
    int oc = idx / KTOT;
    int k  = idx - oc * KTOT;
    int tap = k >> 8;
    int c   = k & 127;        // hi and lo planes share the sign
    float v = w[((size_t)oc * CI + c) * 9 + tap];
    g_wb[idx] = __float2bfloat16_rn(v >= 0.0f ? 1.0f : -1.0f);
}

// ---------------- main kernel ----------------
__device__ __forceinline__ uint32_t smem_u32(const void* p) {
    uint32_t a;
    asm("{ .reg .u64 t; cvta.to.shared.u64 t, %1; cvt.u32.u64 %0, t; }" : "=r"(a) : "l"(p));
    return a;
}
__device__ __forceinline__ void cp16(uint32_t dst, const void* src) {
    asm volatile("cp.async.cg.shared.global [%0], [%1], 16;" :: "r"(dst), "l"(src));
}
#define CP_COMMIT() asm volatile("cp.async.commit_group;" ::: "memory")
#define CP_WAIT1()  asm volatile("cp.async.wait_group 1;" ::: "memory")

__device__ __forceinline__ void ldsm4(uint32_t* r, uint32_t addr) {
    asm volatile("ldmatrix.sync.aligned.m8n8.x4.shared.b16 {%0,%1,%2,%3}, [%4];"
        : "=r"(r[0]), "=r"(r[1]), "=r"(r[2]), "=r"(r[3]) : "r"(addr));
}
__device__ __forceinline__ void mma16816(float* c, const uint32_t* a, uint32_t b0, uint32_t b1) {
    asm volatile("mma.sync.aligned.m16n8k16.row.col.f32.bf16.bf16.f32 "
        "{%0,%1,%2,%3}, {%4,%5,%6,%7}, {%8,%9}, {%0,%1,%2,%3};"
        : "+f"(c[0]), "+f"(c[1]), "+f"(c[2]), "+f"(c[3])
        : "r"(a[0]), "r"(a[1]), "r"(a[2]), "r"(a[3]), "r"(b0), "r"(b1));
}

#define STAGES 3
#define A_ST  16384                 // 128 pix x 64 k x bf16
#define B_ST  32768                 // 256 oc  x 64 k x bf16
#define ST_BYTES (A_ST + B_ST)      // 48 KB / stage
#define SMEM_SZ (STAGES * ST_BYTES) // 144 KB

__global__ __launch_bounds__(512, 1)
void binconv_hmma_kernel(const float* __restrict__ bias, float* __restrict__ out) {
    extern __shared__ char smem[];
    const uint32_t sb = smem_u32(smem);

    const int tid  = threadIdx.x;
    const int wid  = tid >> 5;
    const int lane = tid & 31;
    const int q0   = blockIdx.x * 128;

    // ---- producer addressing ----
    // A: 1024 16B-units/stage: unit u -> pixel=u>>3, seg=u&7 (seg = kb*2+khalf, klocal=seg*8)
    // each thread handles u = tid and u = tid+512
    size_t xrow[2];
    uint32_t adst[2];
#pragma unroll
    for (int j = 0; j < 2; j++) {
        int u = tid + j * 512;
        int pix = u >> 3, seg = u & 7;
        int q  = q0 + pix;
        int n_ = q / PIXN;
        int r_ = q - n_ * PIXN;
        int h_ = r_ / HH;
        int w_ = r_ - h_ * HH;
        xrow[j] = ((size_t)(n_ * HP + h_) * HP + w_) * 256 + seg * 8;
        adst[j] = sb + (uint32_t)(seg * 128 + pix) * 16;
    }
    // B: 2048 units/stage: unit u -> oc=u>>3, seg=u&7; threads do u = tid + 512*j, j=0..3
    size_t bsrc[4];
    uint32_t bdst[4];
#pragma unroll
    for (int j = 0; j < 4; j++) {
        int u = tid + j * 512;
        int oc = u >> 3, seg = u & 7;
        bsrc[j] = (size_t)oc * KTOT + seg * 8;
        bdst[j] = sb + A_ST + (uint32_t)(seg * 256 + oc) * 16;
    }

    // warp tiling: 4 (M) x 4 (N); warp tile 32 x 64
    const int wm = (wid & 3) * 32;
    const int wn = (wid >> 2) * 64;

    float acc[2][8][4];
#pragma unroll
    for (int mi = 0; mi < 2; mi++)
#pragma unroll
        for (int nb = 0; nb < 8; nb++)
#pragma unroll
            for (int j = 0; j < 4; j++) acc[mi][nb][j] = 0.0f;

    auto issue = [&](int it) {
        const uint32_t soff = (uint32_t)(it % STAGES) * ST_BYTES;
        const int tap = it >> 2;
        const int sub = it & 3;
        const int dh = tap / 3, dw = tap - dh * 3;
        const size_t aoff = ((size_t)dh * HP + dw) * 256 + sub * 64;
#pragma unroll
        for (int j = 0; j < 2; j++)
            cp16(adst[j] + soff, g_xp + xrow[j] + aoff);
        const size_t boff = (size_t)it * 64;
#pragma unroll
        for (int j = 0; j < 4; j++)
            cp16(bdst[j] + soff, g_wb + bsrc[j] + boff);
        CP_COMMIT();
    };

    issue(0);
    issue(1);

    // ldmatrix lane addressing (within a k16 block)
    const uint32_t a_lrow = (uint32_t)((lane >> 4) * 128 + (lane & 15)) * 16;
    const uint32_t b_lrow = (uint32_t)(((lane >> 3) & 1) * 256 + (lane & 7) + ((lane >> 4) << 3)) * 16;

    for (int it = 0; it < NITER; it++) {
        const uint32_t soff = (uint32_t)(it % STAGES) * ST_BYTES;
        CP_WAIT1();
        __syncthreads();
        if (it + 2 < NITER) issue(it + 2);
        else CP_COMMIT();   // keep group count consistent so WAIT1 covers the real tail

#pragma unroll
        for (int kb = 0; kb < 4; kb++) {
            uint32_t af[2][4], bf[4][4];
#pragma unroll
            for (int mi = 0; mi < 2; mi++)
                ldsm4(af[mi], sb + soff + kb * 4096 + a_lrow + (uint32_t)(wm + mi * 16) * 16);
#pragma unroll
            for (int nj = 0; nj < 4; nj++)
                ldsm4(bf[nj], sb + A_ST + soff + kb * 8192 + b_lrow + (uint32_t)(wn + nj * 16) * 16);
#pragma unroll
            for (int mi = 0; mi < 2; mi++)
#pragma unroll
                for (int nb = 0; nb < 8; nb++) {
                    const uint32_t* bp = bf[nb >> 1];
                    if (nb & 1) mma16816(acc[mi][nb], af[mi], bp[2], bp[3]);
                    else        mma16816(acc[mi][nb], af[mi], bp[0], bp[1]);
                }
        }
    }

    // ---------------- epilogue: fused bias, coalesced NCHW stores ----------------
    const int qr  = lane >> 2;           // 0..7 (pixel within 8)
    const int oc2 = (lane & 3) * 2;      // oc pair offset

    float2 bv[8];
#pragma unroll
    for (int nb = 0; nb < 8; nb++)
        bv[nb] = *(const float2*)(bias + wn + nb * 8 + oc2);

#pragma unroll
    for (int mi = 0; mi < 2; mi++) {
#pragma unroll
        for (int half = 0; half < 2; half++) {
            const int p  = q0 + wm + mi * 16 + half * 8 + qr;   // global pixel
            const int n2 = p / PIXN;
            const int rm = p - n2 * PIXN;
            float* ob = out + (size_t)n2 * CO * PIXN + rm;
#pragma unroll
            for (int nb = 0; nb < 8; nb++) {
                const int oc = wn + nb * 8 + oc2;
                ob[(size_t)oc * PIXN]       = acc[mi][nb][half * 2 + 0] + bv[nb].x;
                ob[(size_t)(oc + 1) * PIXN] = acc[mi][nb][half * 2 + 1] + bv[nb].y;
            }
        }
    }
}

// ---------------- launch ----------------
extern "C" void kernel_launch(void* const* d_in, const int* in_sizes, int n_in,
                              void* d_out, int out_size) {
    const float* x      = (const float*)d_in[0];
    const float* weight = (const float*)d_in[1];
    const float* bias   = (const float*)d_in[2];
    float* out          = (float*)d_out;

    cudaFuncSetAttribute(binconv_hmma_kernel,
                         cudaFuncAttributeMaxDynamicSharedMemorySize, SMEM_SZ);

    transform_x_kernel<<<NB * HP, 256>>>(x);
    {
        int total = CO * KTOT;
        transform_w_kernel<<<(total + 255) / 256, 256>>>(weight);
    }
    binconv_hmma_kernel<<<NPIX / 128, 512, SMEM_SZ>>>(bias, out);
}